// round 16
// baseline (speedup 1.0000x reference)
#include <cuda_runtime.h>
#include <cuda_bf16.h>
#include <cstdint>
#include <math.h>

// Problem constants
#define BATCH 2
#define SEQ   2048
#define DIMM  1024
#define NH    16
#define HD    64
#define INNER 1024          // NH*HD
#define QKV3  3072          // 3*INNER
#define ROWS  4096          // BATCH*SEQ
#define NTILES 32           // SEQ/64
#define NKI   32            // GEMM K iterations (K=1024, 32 per iter)

// Scratch (allocation-free rule: __device__ globals)
__device__ float g_qkv[(size_t)ROWS * QKV3];
__device__ float g_q[(size_t)BATCH * NH * SEQ * HD];
__device__ float g_k[(size_t)BATCH * NH * SEQ * HD];
__device__ float g_v[(size_t)BATCH * NH * SEQ * HD];

// Attention packed KV tiles: interleaved {hi0,hi1,lo0,lo1} uint4 slots.
// Per tile: 64 rows x 16 uint4 = 1024 uint4. (R6-verified layout)
__device__ uint4 g_kc4[(size_t)BATCH * NH * NTILES * 1024];
__device__ uint4 g_vc4[(size_t)BATCH * NH * NTILES * 1024];

// GEMM packed operands (mma.sync slot layout, proven).
__device__ uint4 g_apack[(size_t)32 * NKI * 1024];       // mt = 4096/128 = 32
__device__ uint4 g_bpack_qkv[(size_t)24 * NKI * 1024];   // nt = 3072/128
__device__ uint4 g_bpack_out[(size_t)8  * NKI * 1024];   // nt = 1024/128

__device__ __forceinline__ float fast_exp2(float x) {
    float y;
    asm("ex2.approx.ftz.f32 %0, %1;" : "=f"(y) : "f"(x));
    return y;
}

__device__ __forceinline__ void pack_split(float x, float y,
                                           unsigned& hi, unsigned& lo) {
    asm("cvt.rn.bf16x2.f32 %0, %1, %2;" : "=r"(hi) : "f"(y), "f"(x));
    __nv_bfloat162 hb = *(__nv_bfloat162*)&hi;
    float rx = x - __bfloat162float(hb.x);
    float ry = y - __bfloat162float(hb.y);
    asm("cvt.rn.bf16x2.f32 %0, %1, %2;" : "=r"(lo) : "f"(ry), "f"(rx));
}

__device__ __forceinline__ void mma_bf16(float d[4], const unsigned a[4],
                                         uint2 b) {
    asm volatile(
        "mma.sync.aligned.m16n8k16.row.col.f32.bf16.bf16.f32 "
        "{%0,%1,%2,%3}, {%4,%5,%6,%7}, {%8,%9}, {%0,%1,%2,%3};"
        : "+f"(d[0]), "+f"(d[1]), "+f"(d[2]), "+f"(d[3])
        : "r"(a[0]), "r"(a[1]), "r"(a[2]), "r"(a[3]), "r"(b.x), "r"(b.y));
}

// ---------------------------------------------------------------------------
// Pack A [M x 1024] fp32 row-major into MMA A-fragment slot layout. (proven)
// ---------------------------------------------------------------------------
__global__ __launch_bounds__(256) void pack_a_kernel(const float* __restrict__ A)
{
    const int ki = blockIdx.x, mt = blockIdx.y;
    uint4* dst = g_apack + ((size_t)(mt * NKI + ki)) * 1024;
#pragma unroll
    for (int j = 0; j < 2; j++) {
        int s = threadIdx.x + j * 256;
        int mb = s >> 6, ks = (s >> 5) & 1, lane = s & 31;
        int g = lane >> 2, t = lane & 3;
        const float* r0 = A + (size_t)(mt * 128 + mb * 16 + g) * 1024
                            + ki * 32 + ks * 16 + 2 * t;
        const float* r1 = r0 + 8 * 1024;
        float2 f00 = *(const float2*)r0;
        float2 f10 = *(const float2*)r1;
        float2 f01 = *(const float2*)(r0 + 8);
        float2 f11 = *(const float2*)(r1 + 8);
        uint4 hi, lo;
        pack_split(f00.x, f00.y, hi.x, lo.x);
        pack_split(f10.x, f10.y, hi.y, lo.y);
        pack_split(f01.x, f01.y, hi.z, lo.z);
        pack_split(f11.x, f11.y, hi.w, lo.w);
        dst[s]       = hi;
        dst[512 + s] = lo;
    }
}

// ---------------------------------------------------------------------------
// Pack B [1024 x N] fp32 row-major into MMA B-fragment slot layout. (proven)
// ---------------------------------------------------------------------------
__global__ __launch_bounds__(256) void pack_b_kernel(
    const float* __restrict__ B, uint4* __restrict__ dst0, int N)
{
    const int ki = blockIdx.x, nt = blockIdx.y;
    uint4* dst = dst0 + ((size_t)(nt * NKI + ki)) * 1024;
#pragma unroll
    for (int j = 0; j < 4; j++) {
        int s = threadIdx.x + j * 256;
        int nb = s >> 6, ks = (s >> 5) & 1, lane = s & 31;
        int g = lane >> 2, t = lane & 3;
        int n = nt * 128 + nb * 8 + g;
        int kk = ki * 32 + ks * 16 + 2 * t;
        const float* p = B + (size_t)kk * N + n;
        float b0 = p[0];
        float b1 = p[N];
        float b2 = p[8 * (size_t)N];
        float b3 = p[9 * (size_t)N];
        uint4 v;
        pack_split(b0, b1, v.x, v.z);
        pack_split(b2, b3, v.y, v.w);
        dst[s] = v;
    }
}

// ---------------------------------------------------------------------------
// bf16x3 GEMM: C[M,N] = A@B + bias. Proven R5 version, untouched.
// ---------------------------------------------------------------------------
__global__ __launch_bounds__(256, 2) void gemm_bf16x3(
    const uint4* __restrict__ gB, const float* __restrict__ bias,
    float* __restrict__ C, int N)
{
    __shared__ uint4 sA[1024];
    __shared__ uint4 sB[1024];

    const int tid = threadIdx.x;
    const int w = tid >> 5, lane = tid & 31;
    const int g = lane >> 2, t = lane & 3;
    const int wm = w >> 1, wn = w & 1;
    const int nt = blockIdx.x, mt = blockIdx.y;

    const uint4* aSrc = g_apack + (size_t)(mt * NKI) * 1024;
    const uint4* bSrc = gB + (size_t)(nt * NKI) * 1024;

    float acc[2][8][4];
#pragma unroll
    for (int mb = 0; mb < 2; mb++)
#pragma unroll
        for (int nb = 0; nb < 8; nb++)
#pragma unroll
            for (int i = 0; i < 4; i++) acc[mb][nb][i] = 0.f;

    for (int ki = 0; ki < NKI; ki++) {
        __syncthreads();
#pragma unroll
        for (int j = 0; j < 4; j++) {
            sA[tid + j * 256] = aSrc[(size_t)ki * 1024 + tid + j * 256];
            sB[tid + j * 256] = bSrc[(size_t)ki * 1024 + tid + j * 256];
        }
        __syncthreads();

#pragma unroll
        for (int ks = 0; ks < 2; ks++) {
            unsigned ah[2][4], al[2][4];
#pragma unroll
            for (int mb = 0; mb < 2; mb++) {
                int slot = (wm * 2 + mb) * 64 + ks * 32 + lane;
                uint4 hv = sA[slot];
                uint4 lv = sA[512 + slot];
                ah[mb][0] = hv.x; ah[mb][1] = hv.y;
                ah[mb][2] = hv.z; ah[mb][3] = hv.w;
                al[mb][0] = lv.x; al[mb][1] = lv.y;
                al[mb][2] = lv.z; al[mb][3] = lv.w;
            }
#pragma unroll
            for (int nb = 0; nb < 8; nb++) {
                int slot = (wn * 8 + nb) * 64 + ks * 32 + lane;
                uint4 bv = sB[slot];
                uint2 bh = make_uint2(bv.x, bv.y);
                uint2 bl = make_uint2(bv.z, bv.w);
#pragma unroll
                for (int mb = 0; mb < 2; mb++) {
                    mma_bf16(acc[mb][nb], ah[mb], bh);
                    mma_bf16(acc[mb][nb], al[mb], bh);
                    mma_bf16(acc[mb][nb], ah[mb], bl);
                }
            }
        }
    }

#pragma unroll
    for (int mb = 0; mb < 2; mb++) {
        int r0 = mt * 128 + wm * 32 + mb * 16 + g;
#pragma unroll
        for (int nb = 0; nb < 8; nb++) {
            int c = nt * 128 + wn * 64 + nb * 8 + 2 * t;
            float bx = bias[c], by = bias[c + 1];
            float2 v0, v1;
            v0.x = acc[mb][nb][0] + bx; v0.y = acc[mb][nb][1] + by;
            v1.x = acc[mb][nb][2] + bx; v1.y = acc[mb][nb][3] + by;
            *(float2*)(C + (size_t)r0 * N + c)       = v0;
            *(float2*)(C + (size_t)(r0 + 8) * N + c) = v1;
        }
    }
}

// ---------------------------------------------------------------------------
// Preprocess: RMSNorm + RoPE + history key scale, transpose (proven, unchanged)
// ---------------------------------------------------------------------------
__global__ __launch_bounds__(256) void preprocess_kernel(
    const float* __restrict__ qkv, const float* __restrict__ rot,
    const float* __restrict__ nqw, const float* __restrict__ nkw,
    const float* __restrict__ hks, const int* __restrict__ oclp,
    float* __restrict__ gq, float* __restrict__ gk, float* __restrict__ gv)
{
    const int row = blockIdx.x;
    const int b = row >> 11;
    const int s = row & 2047;
    const int tid = threadIdx.x;
    const float* base = qkv + (size_t)row * QKV3;

    float sq = 0.f, sk = 0.f;
#pragma unroll
    for (int it = 0; it < 4; it++) {
        int i = tid + it * 256;
        float qv = base[i];
        float kv = base[INNER + i];
        sq = fmaf(qv, qv, sq);
        sk = fmaf(kv, kv, sk);
    }
#pragma unroll
    for (int off = 16; off > 0; off >>= 1) {
        sq += __shfl_xor_sync(0xffffffffu, sq, off);
        sk += __shfl_xor_sync(0xffffffffu, sk, off);
    }
    __shared__ float rq[8], rk[8];
    const int wid = tid >> 5, lane = tid & 31;
    if (lane == 0) { rq[wid] = sq; rk[wid] = sk; }
    __syncthreads();
    float tq = 0.f, tk = 0.f;
#pragma unroll
    for (int w = 0; w < 8; w++) { tq += rq[w]; tk += rk[w]; }
    const float invq = rsqrtf(tq * (1.f / 1024.f) + 1e-5f);
    const float invk = rsqrtf(tk * (1.f / 1024.f) + 1e-5f);

    const int hist = SEQ - *oclp;
    const float* rrow = rot + (size_t)row * (2 * HD);

#pragma unroll
    for (int it = 0; it < 2; it++) {
        int p = tid + it * 256;
        int hh = p >> 5;
        int i = p & 31;
        int e0 = hh * HD + 2 * i;
        int e1 = e0 + 1;
        float ce = rrow[2 * i];
        float so = rrow[HD + 2 * i + 1];
        float q0 = base[e0] * invq * nqw[e0];
        float q1 = base[e1] * invq * nqw[e1];
        float k0 = base[INNER + e0] * invk * nkw[e0];
        float k1 = base[INNER + e1] * invk * nkw[e1];
        float qo0 = q0 * ce - q1 * so;
        float qo1 = q0 * so + q1 * ce;
        float ko0 = k0 * ce - k1 * so;
        float ko1 = k0 * so + k1 * ce;
        float ksc = 1.f;
        if (s < hist) {
            float hv = hks[hh];
            float sig = 1.f / (1.f + __expf(-hv));
            ksc = 1.f + sig * 9.f;
        }
        size_t dst = (((size_t)b * NH + hh) * SEQ + s) * HD + 2 * i;
        gq[dst]     = qo0;
        gq[dst + 1] = qo1;
        gk[dst]     = ko0 * ksc;
        gk[dst + 1] = ko1 * ksc;
    }
#pragma unroll
    for (int it = 0; it < 4; it++) {
        int d = tid + it * 256;
        int hh = d >> 6;
        int dd = d & 63;
        gv[(((size_t)b * NH + hh) * SEQ + s) * HD + dd] = base[2 * INNER + d];
    }
}

// ---------------------------------------------------------------------------
// Pack K,V into interleaved {hi,hi,lo,lo} uint4 MMA-slot tiles (R6-verified).
// ---------------------------------------------------------------------------
__global__ __launch_bounds__(256) void pack_kv_kernel(
    const float* __restrict__ gk, const float* __restrict__ gv)
{
    const int kt = blockIdx.x, h = blockIdx.y, b = blockIdx.z;
    const int tid = threadIdx.x;
    const size_t tb = ((size_t)(b * NH + h) * NTILES + kt);
    const float* ksrc = gk + ((size_t)(b * NH + h) * SEQ + kt * 64) * HD;
    const float* vsrc = gv + ((size_t)(b * NH + h) * SEQ + kt * 64) * HD;

    __shared__ float Vsm[64][68];
#pragma unroll
    for (int i = 0; i < 4; i++) {
        int idx = tid + 256 * i;
        int row = idx >> 4, c4 = idx & 15;
        *(float4*)&Vsm[row][c4 * 4] = ((const float4*)vsrc)[idx];
    }
    __syncthreads();

    const int r = tid >> 2;               // row (key for K, d for V)
    const int grp = tid & 3;              // c chunk

    uint4* kdst = g_kc4 + tb * 1024 + r * 16;
    uint4* vdst = g_vc4 + tb * 1024 + r * 16;

    const float* krow = ksrc + r * HD;
#pragma unroll
    for (int tig = 0; tig < 4; tig++) {
        int d0 = grp * 16 + 2 * tig;
        float2 p0 = *(const float2*)(krow + d0);
        float2 p1 = *(const float2*)(krow + d0 + 8);
        uint4 kv;
        pack_split(p0.x, p0.y, kv.x, kv.z);
        pack_split(p1.x, p1.y, kv.y, kv.w);
        kdst[grp * 4 + tig] = kv;
        float v0 = Vsm[d0][r], v1 = Vsm[d0 + 1][r];
        float v2 = Vsm[d0 + 8][r], v3 = Vsm[d0 + 9][r];
        uint4 vv;
        pack_split(v0, v1, vv.x, vv.z);
        pack_split(v2, v3, vv.y, vv.w);
        vdst[grp * 4 + tig] = vv;
    }
}

// ---------------------------------------------------------------------------
// Flash attention, bf16x3 tensor cores, WARP-SPECIALIZED producer/consumer.
// 160 threads: warps 0-3 compute (32 queries each), warp 4 = producer that
// fills a double-buffered smem stage (2 x 40KB dynamic) with plain LDG/STS.
// Compute warps never touch global in the mainloop -> no exposed load phase,
// no LSU contention with HMMA issue. Named-barrier full/free protocol.
// Softmax(mb) -> PV(mb) reorder lets PV HMMAs overlap next mb's ALU chain.
// Epilogue writes packed-A (g_apack) directly.
// ---------------------------------------------------------------------------
#define KVROW 20                        // uint4 row stride (16 data + 4 pad)
#define STAGE_U4 (2 * 64 * KVROW)       // K+V per stage = 2560 uint4 = 40KB

extern __shared__ uint4 dynsm[];

#define BAR_SYNC(id)   asm volatile("bar.sync %0, %1;"   :: "r"(id), "r"(160) : "memory")
#define BAR_ARRIVE(id) asm volatile("bar.arrive %0, %1;" :: "r"(id), "r"(160) : "memory")

__global__ __launch_bounds__(160, 2) void attn_tc_kernel(
    const float* __restrict__ gq)
{
    const int tid  = threadIdx.x;
    const int w    = tid >> 5;      // 0..4
    const int lane = tid & 31;
    const int h = blockIdx.y, b = blockIdx.z;
    const size_t tbase = ((size_t)(b * NH + h) * NTILES) * 1024;

    // ---------------- Producer warp ----------------
    if (w == 4) {
        for (int kt = 0; kt < NTILES; kt++) {
            const int st = kt & 1;
            if (kt >= 2) BAR_SYNC(3 + st);          // wait stage free
            uint4* Ks = dynsm + st * STAGE_U4;
            uint4* Vs = Ks + 64 * KVROW;
            const size_t tb = tbase + (size_t)kt * 1024;
#pragma unroll
            for (int i = 0; i < 32; i++) {
                int idx = lane + 32 * i;            // 1024 per array
                int row = idx >> 4, s4 = idx & 15;
                Ks[row * KVROW + s4] = g_kc4[tb + idx];
                Vs[row * KVROW + s4] = g_vc4[tb + idx];
            }
            BAR_ARRIVE(1 + st);                     // mark stage full
        }
        return;
    }

    // ---------------- Compute warps (0..3) ----------------
    const int g    = lane >> 2;     // 0..7
    const int tig  = lane & 3;      // 0..3
    const int qb = blockIdx.x * 128;
    const size_t bh = ((size_t)b * NH + h) * SEQ;

    const float SC = 0.125f * 1.4426950408889634f;  // 1/sqrt(64)*log2(e)

    // Q A-fragments (hi/lo) for 2 m-blocks of 16 rows.
    unsigned qhi[2][4][4], qlo[2][4][4];
#pragma unroll
    for (int mb = 0; mb < 2; mb++) {
        const float* q0 = gq + (bh + qb + w * 32 + mb * 16 + g) * HD;
        const float* q1 = q0 + 8 * HD;
#pragma unroll
        for (int c = 0; c < 4; c++) {
            int d0 = 16 * c + 2 * tig;
            float2 f00 = *(const float2*)(q0 + d0);
            float2 f10 = *(const float2*)(q1 + d0);
            float2 f01 = *(const float2*)(q0 + d0 + 8);
            float2 f11 = *(const float2*)(q1 + d0 + 8);
            pack_split(f00.x * SC, f00.y * SC, qhi[mb][c][0], qlo[mb][c][0]);
            pack_split(f10.x * SC, f10.y * SC, qhi[mb][c][1], qlo[mb][c][1]);
            pack_split(f01.x * SC, f01.y * SC, qhi[mb][c][2], qlo[mb][c][2]);
            pack_split(f11.x * SC, f11.y * SC, qhi[mb][c][3], qlo[mb][c][3]);
        }
    }

    float o[2][8][4];
#pragma unroll
    for (int mb = 0; mb < 2; mb++)
#pragma unroll
        for (int nt = 0; nt < 8; nt++)
#pragma unroll
            for (int i = 0; i < 4; i++) o[mb][nt][i] = 0.f;
    float mst[2][2] = {{-1e30f, -1e30f}, {-1e30f, -1e30f}};
    float lst[2][2] = {{0.f, 0.f}, {0.f, 0.f}};

    for (int kt = 0; kt < NTILES; kt++) {
        const int st = kt & 1;
        BAR_SYNC(1 + st);                           // wait stage full
        const uint4* Kc = dynsm + st * STAGE_U4;
        const uint4* Vc = Kc + 64 * KVROW;

        // S = Q @ K^T: each K fragment (one LDS.128) feeds both m-blocks.
        float s[2][8][4];
#pragma unroll
        for (int jn = 0; jn < 8; jn++) {
#pragma unroll
            for (int i = 0; i < 4; i++) { s[0][jn][i] = 0.f; s[1][jn][i] = 0.f; }
            const uint4* kr = Kc + (jn * 8 + g) * KVROW;
#pragma unroll
            for (int c = 0; c < 4; c++) {
                uint4 kv = kr[c * 4 + tig];
                uint2 bh_ = make_uint2(kv.x, kv.y);
                uint2 bl_ = make_uint2(kv.z, kv.w);
                mma_bf16(s[0][jn], qhi[0][c], bh_);
                mma_bf16(s[0][jn], qlo[0][c], bh_);
                mma_bf16(s[0][jn], qhi[0][c], bl_);
                mma_bf16(s[1][jn], qhi[1][c], bh_);
                mma_bf16(s[1][jn], qlo[1][c], bh_);
                mma_bf16(s[1][jn], qhi[1][c], bl_);
            }
        }

        // Per m-block: softmax then immediately PV (HMMA overlaps next mb ALU)
#pragma unroll
        for (int mb = 0; mb < 2; mb++) {
            float rmax0 = s[mb][0][0], rmax1 = s[mb][0][2];
#pragma unroll
            for (int jn = 0; jn < 8; jn++) {
                rmax0 = fmaxf(rmax0, fmaxf(s[mb][jn][0], s[mb][jn][1]));
                rmax1 = fmaxf(rmax1, fmaxf(s[mb][jn][2], s[mb][jn][3]));
            }
            rmax0 = fmaxf(rmax0, __shfl_xor_sync(0xffffffffu, rmax0, 1));
            rmax0 = fmaxf(rmax0, __shfl_xor_sync(0xffffffffu, rmax0, 2));
            rmax1 = fmaxf(rmax1, __shfl_xor_sync(0xffffffffu, rmax1, 1));
            rmax1 = fmaxf(rmax1, __shfl_xor_sync(0xffffffffu, rmax1, 2));

            float mn0 = fmaxf(mst[mb][0], rmax0);
            float mn1 = fmaxf(mst[mb][1], rmax1);
            float corr0 = fast_exp2(mst[mb][0] - mn0);
            float corr1 = fast_exp2(mst[mb][1] - mn1);
            mst[mb][0] = mn0; mst[mb][1] = mn1;

            float ps0 = 0.f, ps1 = 0.f;
#pragma unroll
            for (int jn = 0; jn < 8; jn++) {
                s[mb][jn][0] = fast_exp2(s[mb][jn][0] - mn0);
                s[mb][jn][1] = fast_exp2(s[mb][jn][1] - mn0);
                s[mb][jn][2] = fast_exp2(s[mb][jn][2] - mn1);
                s[mb][jn][3] = fast_exp2(s[mb][jn][3] - mn1);
                ps0 += s[mb][jn][0] + s[mb][jn][1];
                ps1 += s[mb][jn][2] + s[mb][jn][3];
            }
            lst[mb][0] = lst[mb][0] * corr0 + ps0;
            lst[mb][1] = lst[mb][1] * corr1 + ps1;
#pragma unroll
            for (int nt = 0; nt < 8; nt++) {
                o[mb][nt][0] *= corr0;
                o[mb][nt][1] *= corr0;
                o[mb][nt][2] *= corr1;
                o[mb][nt][3] *= corr1;
            }

            unsigned phi[4][4], plo[4][4];
#pragma unroll
            for (int c = 0; c < 4; c++) {
                pack_split(s[mb][2*c][0],   s[mb][2*c][1],   phi[c][0], plo[c][0]);
                pack_split(s[mb][2*c][2],   s[mb][2*c][3],   phi[c][1], plo[c][1]);
                pack_split(s[mb][2*c+1][0], s[mb][2*c+1][1], phi[c][2], plo[c][2]);
                pack_split(s[mb][2*c+1][2], s[mb][2*c+1][3], phi[c][3], plo[c][3]);
            }

            // O(mb) += P(mb) @ V
#pragma unroll
            for (int nt = 0; nt < 8; nt++) {
                const uint4* vr = Vc + (nt * 8 + g) * KVROW;
#pragma unroll
                for (int c = 0; c < 4; c++) {
                    uint4 vv = vr[c * 4 + tig];
                    uint2 bh_ = make_uint2(vv.x, vv.y);
                    uint2 bl_ = make_uint2(vv.z, vv.w);
                    mma_bf16(o[mb][nt], phi[c], bh_);
                    mma_bf16(o[mb][nt], plo[c], bh_);
                    mma_bf16(o[mb][nt], phi[c], bl_);
                }
            }
        }

        BAR_ARRIVE(3 + st);                         // mark stage free
    }

    // Epilogue: normalize, write packed-A for output projection.
    const int mt = b * (SEQ / 128) + blockIdx.x;
#pragma unroll
    for (int mb = 0; mb < 2; mb++) {
        float li0 = lst[mb][0], li1 = lst[mb][1];
        li0 += __shfl_xor_sync(0xffffffffu, li0, 1);
        li0 += __shfl_xor_sync(0xffffffffu, li0, 2);
        li1 += __shfl_xor_sync(0xffffffffu, li1, 1);
        li1 += __shfl_xor_sync(0xffffffffu, li1, 2);
        const float inv0 = 1.f / li0;
        const float inv1 = 1.f / li1;
        const int mbp = 2 * w + mb;
#pragma unroll
        for (int half = 0; half < 2; half++) {
            const int ki = 2 * h + half;
            uint4* dst = g_apack + ((size_t)(mt * NKI + ki)) * 1024
                                 + mbp * 64 + lane;
#pragma unroll
            for (int ks = 0; ks < 2; ks++) {
                const int nt = half * 4 + ks * 2;
                uint4 hi, lo;
                pack_split(o[mb][nt][0] * inv0,   o[mb][nt][1] * inv0,   hi.x, lo.x);
                pack_split(o[mb][nt][2] * inv1,   o[mb][nt][3] * inv1,   hi.y, lo.y);
                pack_split(o[mb][nt+1][0] * inv0, o[mb][nt+1][1] * inv0, hi.z, lo.z);
                pack_split(o[mb][nt+1][2] * inv1, o[mb][nt+1][3] * inv1, hi.w, lo.w);
                dst[ks * 32]       = hi;
                dst[ks * 32 + 512] = lo;
            }
        }
    }
}

// ---------------------------------------------------------------------------
extern "C" void kernel_launch(void* const* d_in, const int* in_sizes, int n_in,
                              void* d_out, int out_size)
{
    const float* hidden = (const float*)d_in[0];
    const float* rot    = (const float*)d_in[1];
    const float* w_qkv  = (const float*)d_in[2];
    const float* b_qkv  = (const float*)d_in[3];
    const float* nqw    = (const float*)d_in[4];
    const float* nkw    = (const float*)d_in[5];
    const float* w_out  = (const float*)d_in[6];
    const float* b_out  = (const float*)d_in[7];
    const float* hks    = (const float*)d_in[8];
    const int*   ocl    = (const int*)d_in[9];
    float* out = (float*)d_out;

    static float *p_qkv = nullptr, *p_q = nullptr, *p_k = nullptr,
                 *p_v = nullptr;
    static uint4 *p_bq = nullptr, *p_bo = nullptr;
    if (!p_qkv) {
        cudaGetSymbolAddress((void**)&p_qkv,  g_qkv);
        cudaGetSymbolAddress((void**)&p_q,    g_q);
        cudaGetSymbolAddress((void**)&p_k,    g_k);
        cudaGetSymbolAddress((void**)&p_v,    g_v);
        cudaGetSymbolAddress((void**)&p_bq,   g_bpack_qkv);
        cudaGetSymbolAddress((void**)&p_bo,   g_bpack_out);
        // Opt-in to >48KB dynamic smem (outside graph capture).
        cudaFuncSetAttribute(attn_tc_kernel,
            cudaFuncAttributeMaxDynamicSharedMemorySize, 2 * STAGE_U4 * 16);
    }

    const int ATTN_SMEM = 2 * STAGE_U4 * 16;   // 80KB

    // 1) Pack operands
    pack_b_kernel<<<dim3(NKI, QKV3 / 128), 256>>>(w_qkv, p_bq, QKV3);
    pack_b_kernel<<<dim3(NKI, DIMM / 128), 256>>>(w_out, p_bo, DIMM);
    pack_a_kernel<<<dim3(NKI, ROWS / 128), 256>>>(hidden);

    // 2) QKV projection (bf16x3 tensor cores)
    gemm_bf16x3<<<dim3(QKV3 / 128, ROWS / 128), 256>>>(p_bq, b_qkv, p_qkv, QKV3);

    // 3) RMSNorm + RoPE + history scale + transpose
    preprocess_kernel<<<ROWS, 256>>>(p_qkv, rot, nqw, nkw, hks, ocl,
                                     p_q, p_k, p_v);

    // 4) Pack K,V for attention (interleaved hi/lo)
    pack_kv_kernel<<<dim3(NTILES, NH, BATCH), 256>>>(p_k, p_v);

    // 5) Attention (warp-specialized producer, double-buffered) -> packed A
    attn_tc_kernel<<<dim3(SEQ / 128, NH, BATCH), 160, ATTN_SMEM>>>(p_q);

    // 6) Output projection (bf16x3 tensor cores)
    gemm_bf16x3<<<dim3(DIMM / 128, ROWS / 128), 256>>>(p_bo, b_out, out, DIMM);
}

// round 17
// speedup vs baseline: 1.1418x; 1.1418x over previous
#include <cuda_runtime.h>
#include <cuda_bf16.h>
#include <cstdint>
#include <math.h>

// Problem constants
#define BATCH 2
#define SEQ   2048
#define DIMM  1024
#define NH    16
#define HD    64
#define INNER 1024          // NH*HD
#define QKV3  3072          // 3*INNER
#define ROWS  4096          // BATCH*SEQ
#define NTILES 32           // SEQ/64
#define NKI   32            // GEMM K iterations (K=1024, 32 per iter)

// Scratch (allocation-free rule: __device__ globals)
__device__ float g_qkv[(size_t)ROWS * QKV3];
__device__ float g_q[(size_t)BATCH * NH * SEQ * HD];
__device__ float g_k[(size_t)BATCH * NH * SEQ * HD];
__device__ float g_v[(size_t)BATCH * NH * SEQ * HD];

// Attention packed KV tiles: interleaved {hi0,hi1,lo0,lo1} uint4 slots.
__device__ uint4 g_kc4[(size_t)BATCH * NH * NTILES * 1024];
__device__ uint4 g_vc4[(size_t)BATCH * NH * NTILES * 1024];

// GEMM packed operands (mma.sync slot layout, proven).
__device__ uint4 g_apack[(size_t)32 * NKI * 1024];       // mt = 4096/128 = 32
__device__ uint4 g_bpack_qkv[(size_t)24 * NKI * 1024];   // nt = 3072/128
__device__ uint4 g_bpack_out[(size_t)8  * NKI * 1024];   // nt = 1024/128

__device__ __forceinline__ float fast_exp2(float x) {
    float y;
    asm("ex2.approx.ftz.f32 %0, %1;" : "=f"(y) : "f"(x));
    return y;
}

__device__ __forceinline__ void pack_split(float x, float y,
                                           unsigned& hi, unsigned& lo) {
    asm("cvt.rn.bf16x2.f32 %0, %1, %2;" : "=r"(hi) : "f"(y), "f"(x));
    __nv_bfloat162 hb = *(__nv_bfloat162*)&hi;
    float rx = x - __bfloat162float(hb.x);
    float ry = y - __bfloat162float(hb.y);
    asm("cvt.rn.bf16x2.f32 %0, %1, %2;" : "=r"(lo) : "f"(ry), "f"(rx));
}

__device__ __forceinline__ void mma_bf16(float d[4], const unsigned a[4],
                                         uint2 b) {
    asm volatile(
        "mma.sync.aligned.m16n8k16.row.col.f32.bf16.bf16.f32 "
        "{%0,%1,%2,%3}, {%4,%5,%6,%7}, {%8,%9}, {%0,%1,%2,%3};"
        : "+f"(d[0]), "+f"(d[1]), "+f"(d[2]), "+f"(d[3])
        : "r"(a[0]), "r"(a[1]), "r"(a[2]), "r"(a[3]), "r"(b.x), "r"(b.y));
}

// One-time anti-phase stagger for co-resident CTAs: odd-parity CTAs burn
// ~half a pipeline period once so the two CTAs on an SM interleave their
// load and MMA phases instead of loading simultaneously.
__device__ __forceinline__ void stagger(int parity, long long cyc) {
    if (parity) {
        long long t0 = clock64();
        while (clock64() - t0 < cyc) { }
    }
}

// ---------------------------------------------------------------------------
// Pack A [M x 1024] fp32 row-major into MMA A-fragment slot layout. (proven)
// ---------------------------------------------------------------------------
__global__ __launch_bounds__(256) void pack_a_kernel(const float* __restrict__ A)
{
    const int ki = blockIdx.x, mt = blockIdx.y;
    uint4* dst = g_apack + ((size_t)(mt * NKI + ki)) * 1024;
#pragma unroll
    for (int j = 0; j < 2; j++) {
        int s = threadIdx.x + j * 256;
        int mb = s >> 6, ks = (s >> 5) & 1, lane = s & 31;
        int g = lane >> 2, t = lane & 3;
        const float* r0 = A + (size_t)(mt * 128 + mb * 16 + g) * 1024
                            + ki * 32 + ks * 16 + 2 * t;
        const float* r1 = r0 + 8 * 1024;
        float2 f00 = *(const float2*)r0;
        float2 f10 = *(const float2*)r1;
        float2 f01 = *(const float2*)(r0 + 8);
        float2 f11 = *(const float2*)(r1 + 8);
        uint4 hi, lo;
        pack_split(f00.x, f00.y, hi.x, lo.x);
        pack_split(f10.x, f10.y, hi.y, lo.y);
        pack_split(f01.x, f01.y, hi.z, lo.z);
        pack_split(f11.x, f11.y, hi.w, lo.w);
        dst[s]       = hi;
        dst[512 + s] = lo;
    }
}

// ---------------------------------------------------------------------------
// Pack B [1024 x N] fp32 row-major into MMA B-fragment slot layout. (proven)
// ---------------------------------------------------------------------------
__global__ __launch_bounds__(256) void pack_b_kernel(
    const float* __restrict__ B, uint4* __restrict__ dst0, int N)
{
    const int ki = blockIdx.x, nt = blockIdx.y;
    uint4* dst = dst0 + ((size_t)(nt * NKI + ki)) * 1024;
#pragma unroll
    for (int j = 0; j < 4; j++) {
        int s = threadIdx.x + j * 256;
        int nb = s >> 6, ks = (s >> 5) & 1, lane = s & 31;
        int g = lane >> 2, t = lane & 3;
        int n = nt * 128 + nb * 8 + g;
        int kk = ki * 32 + ks * 16 + 2 * t;
        const float* p = B + (size_t)kk * N + n;
        float b0 = p[0];
        float b1 = p[N];
        float b2 = p[8 * (size_t)N];
        float b3 = p[9 * (size_t)N];
        uint4 v;
        pack_split(b0, b1, v.x, v.z);
        pack_split(b2, b3, v.y, v.w);
        dst[s] = v;
    }
}

// ---------------------------------------------------------------------------
// bf16x3 GEMM: C[M,N] = A@B + bias. Proven R5 version + anti-phase stagger.
// ---------------------------------------------------------------------------
__global__ __launch_bounds__(256, 2) void gemm_bf16x3(
    const uint4* __restrict__ gB, const float* __restrict__ bias,
    float* __restrict__ C, int N)
{
    __shared__ uint4 sA[1024];
    __shared__ uint4 sB[1024];

    const int tid = threadIdx.x;
    const int w = tid >> 5, lane = tid & 31;
    const int g = lane >> 2, t = lane & 3;
    const int wm = w >> 1, wn = w & 1;
    const int nt = blockIdx.x, mt = blockIdx.y;

    // Desync co-resident CTAs: odd CTAs offset by ~half a (load+mma) period.
    stagger((nt + mt) & 1, 2600);

    const uint4* aSrc = g_apack + (size_t)(mt * NKI) * 1024;
    const uint4* bSrc = gB + (size_t)(nt * NKI) * 1024;

    float acc[2][8][4];
#pragma unroll
    for (int mb = 0; mb < 2; mb++)
#pragma unroll
        for (int nb = 0; nb < 8; nb++)
#pragma unroll
            for (int i = 0; i < 4; i++) acc[mb][nb][i] = 0.f;

    for (int ki = 0; ki < NKI; ki++) {
        __syncthreads();
#pragma unroll
        for (int j = 0; j < 4; j++) {
            sA[tid + j * 256] = aSrc[(size_t)ki * 1024 + tid + j * 256];
            sB[tid + j * 256] = bSrc[(size_t)ki * 1024 + tid + j * 256];
        }
        __syncthreads();

#pragma unroll
        for (int ks = 0; ks < 2; ks++) {
            unsigned ah[2][4], al[2][4];
#pragma unroll
            for (int mb = 0; mb < 2; mb++) {
                int slot = (wm * 2 + mb) * 64 + ks * 32 + lane;
                uint4 hv = sA[slot];
                uint4 lv = sA[512 + slot];
                ah[mb][0] = hv.x; ah[mb][1] = hv.y;
                ah[mb][2] = hv.z; ah[mb][3] = hv.w;
                al[mb][0] = lv.x; al[mb][1] = lv.y;
                al[mb][2] = lv.z; al[mb][3] = lv.w;
            }
#pragma unroll
            for (int nb = 0; nb < 8; nb++) {
                int slot = (wn * 8 + nb) * 64 + ks * 32 + lane;
                uint4 bv = sB[slot];
                uint2 bh = make_uint2(bv.x, bv.y);
                uint2 bl = make_uint2(bv.z, bv.w);
#pragma unroll
                for (int mb = 0; mb < 2; mb++) {
                    mma_bf16(acc[mb][nb], ah[mb], bh);
                    mma_bf16(acc[mb][nb], al[mb], bh);
                    mma_bf16(acc[mb][nb], ah[mb], bl);
                }
            }
        }
    }

#pragma unroll
    for (int mb = 0; mb < 2; mb++) {
        int r0 = mt * 128 + wm * 32 + mb * 16 + g;
#pragma unroll
        for (int nb = 0; nb < 8; nb++) {
            int c = nt * 128 + wn * 64 + nb * 8 + 2 * t;
            float bx = bias[c], by = bias[c + 1];
            float2 v0, v1;
            v0.x = acc[mb][nb][0] + bx; v0.y = acc[mb][nb][1] + by;
            v1.x = acc[mb][nb][2] + bx; v1.y = acc[mb][nb][3] + by;
            *(float2*)(C + (size_t)r0 * N + c)       = v0;
            *(float2*)(C + (size_t)(r0 + 8) * N + c) = v1;
        }
    }
}

// ---------------------------------------------------------------------------
// Preprocess: RMSNorm + RoPE + history key scale, transpose (proven, unchanged)
// ---------------------------------------------------------------------------
__global__ __launch_bounds__(256) void preprocess_kernel(
    const float* __restrict__ qkv, const float* __restrict__ rot,
    const float* __restrict__ nqw, const float* __restrict__ nkw,
    const float* __restrict__ hks, const int* __restrict__ oclp,
    float* __restrict__ gq, float* __restrict__ gk, float* __restrict__ gv)
{
    const int row = blockIdx.x;
    const int b = row >> 11;
    const int s = row & 2047;
    const int tid = threadIdx.x;
    const float* base = qkv + (size_t)row * QKV3;

    float sq = 0.f, sk = 0.f;
#pragma unroll
    for (int it = 0; it < 4; it++) {
        int i = tid + it * 256;
        float qv = base[i];
        float kv = base[INNER + i];
        sq = fmaf(qv, qv, sq);
        sk = fmaf(kv, kv, sk);
    }
#pragma unroll
    for (int off = 16; off > 0; off >>= 1) {
        sq += __shfl_xor_sync(0xffffffffu, sq, off);
        sk += __shfl_xor_sync(0xffffffffu, sk, off);
    }
    __shared__ float rq[8], rk[8];
    const int wid = tid >> 5, lane = tid & 31;
    if (lane == 0) { rq[wid] = sq; rk[wid] = sk; }
    __syncthreads();
    float tq = 0.f, tk = 0.f;
#pragma unroll
    for (int w = 0; w < 8; w++) { tq += rq[w]; tk += rk[w]; }
    const float invq = rsqrtf(tq * (1.f / 1024.f) + 1e-5f);
    const float invk = rsqrtf(tk * (1.f / 1024.f) + 1e-5f);

    const int hist = SEQ - *oclp;
    const float* rrow = rot + (size_t)row * (2 * HD);

#pragma unroll
    for (int it = 0; it < 2; it++) {
        int p = tid + it * 256;
        int hh = p >> 5;
        int i = p & 31;
        int e0 = hh * HD + 2 * i;
        int e1 = e0 + 1;
        float ce = rrow[2 * i];
        float so = rrow[HD + 2 * i + 1];
        float q0 = base[e0] * invq * nqw[e0];
        float q1 = base[e1] * invq * nqw[e1];
        float k0 = base[INNER + e0] * invk * nkw[e0];
        float k1 = base[INNER + e1] * invk * nkw[e1];
        float qo0 = q0 * ce - q1 * so;
        float qo1 = q0 * so + q1 * ce;
        float ko0 = k0 * ce - k1 * so;
        float ko1 = k0 * so + k1 * ce;
        float ksc = 1.f;
        if (s < hist) {
            float hv = hks[hh];
            float sig = 1.f / (1.f + __expf(-hv));
            ksc = 1.f + sig * 9.f;
        }
        size_t dst = (((size_t)b * NH + hh) * SEQ + s) * HD + 2 * i;
        gq[dst]     = qo0;
        gq[dst + 1] = qo1;
        gk[dst]     = ko0 * ksc;
        gk[dst + 1] = ko1 * ksc;
    }
#pragma unroll
    for (int it = 0; it < 4; it++) {
        int d = tid + it * 256;
        int hh = d >> 6;
        int dd = d & 63;
        gv[(((size_t)b * NH + hh) * SEQ + s) * HD + dd] = base[2 * INNER + d];
    }
}

// ---------------------------------------------------------------------------
// Pack K,V into interleaved {hi,hi,lo,lo} uint4 MMA-slot tiles (R6-verified).
// ---------------------------------------------------------------------------
__global__ __launch_bounds__(256) void pack_kv_kernel(
    const float* __restrict__ gk, const float* __restrict__ gv)
{
    const int kt = blockIdx.x, h = blockIdx.y, b = blockIdx.z;
    const int tid = threadIdx.x;
    const size_t tb = ((size_t)(b * NH + h) * NTILES + kt);
    const float* ksrc = gk + ((size_t)(b * NH + h) * SEQ + kt * 64) * HD;
    const float* vsrc = gv + ((size_t)(b * NH + h) * SEQ + kt * 64) * HD;

    __shared__ float Vsm[64][68];
#pragma unroll
    for (int i = 0; i < 4; i++) {
        int idx = tid + 256 * i;
        int row = idx >> 4, c4 = idx & 15;
        *(float4*)&Vsm[row][c4 * 4] = ((const float4*)vsrc)[idx];
    }
    __syncthreads();

    const int r = tid >> 2;               // row (key for K, d for V)
    const int grp = tid & 3;              // c chunk

    uint4* kdst = g_kc4 + tb * 1024 + r * 16;
    uint4* vdst = g_vc4 + tb * 1024 + r * 16;

    const float* krow = ksrc + r * HD;
#pragma unroll
    for (int tig = 0; tig < 4; tig++) {
        int d0 = grp * 16 + 2 * tig;
        float2 p0 = *(const float2*)(krow + d0);
        float2 p1 = *(const float2*)(krow + d0 + 8);
        uint4 kv;
        pack_split(p0.x, p0.y, kv.x, kv.z);
        pack_split(p1.x, p1.y, kv.y, kv.w);
        kdst[grp * 4 + tig] = kv;
        float v0 = Vsm[d0][r], v1 = Vsm[d0 + 1][r];
        float v2 = Vsm[d0 + 8][r], v3 = Vsm[d0 + 9][r];
        uint4 vv;
        pack_split(v0, v1, vv.x, vv.z);
        pack_split(v2, v3, vv.y, vv.w);
        vdst[grp * 4 + tig] = vv;
    }
}

// ---------------------------------------------------------------------------
// Flash attention, bf16x3 tensor cores (R15 champion version + stagger).
// 4 warps x 32 queries; interleaved KV LDS.128; single-buffered smem.
// Epilogue writes packed-A (g_apack) directly.
// ---------------------------------------------------------------------------
#define KVROW 20                   // uint4 row stride (16 data + 4 pad)

__global__ __launch_bounds__(128, 2) void attn_tc_kernel(
    const float* __restrict__ gq)
{
    __shared__ uint4 Ksm[64 * KVROW];
    __shared__ uint4 Vsm[64 * KVROW];

    const int tid  = threadIdx.x;
    const int w    = tid >> 5;      // 0..3
    const int lane = tid & 31;
    const int g    = lane >> 2;     // 0..7
    const int tig  = lane & 3;      // 0..3
    const int h = blockIdx.y, b = blockIdx.z;
    const int qb = blockIdx.x * 128;
    const size_t bh = ((size_t)b * NH + h) * SEQ;

    // Desync co-resident CTAs (~half a tile period).
    stagger((blockIdx.x + blockIdx.y + blockIdx.z) & 1, 4200);

    const float SC = 0.125f * 1.4426950408889634f;  // 1/sqrt(64)*log2(e)

    // Q A-fragments (hi/lo) for 2 m-blocks of 16 rows.
    unsigned qhi[2][4][4], qlo[2][4][4];
#pragma unroll
    for (int mb = 0; mb < 2; mb++) {
        const float* q0 = gq + (bh + qb + w * 32 + mb * 16 + g) * HD;
        const float* q1 = q0 + 8 * HD;
#pragma unroll
        for (int c = 0; c < 4; c++) {
            int d0 = 16 * c + 2 * tig;
            float2 f00 = *(const float2*)(q0 + d0);
            float2 f10 = *(const float2*)(q1 + d0);
            float2 f01 = *(const float2*)(q0 + d0 + 8);
            float2 f11 = *(const float2*)(q1 + d0 + 8);
            pack_split(f00.x * SC, f00.y * SC, qhi[mb][c][0], qlo[mb][c][0]);
            pack_split(f10.x * SC, f10.y * SC, qhi[mb][c][1], qlo[mb][c][1]);
            pack_split(f01.x * SC, f01.y * SC, qhi[mb][c][2], qlo[mb][c][2]);
            pack_split(f11.x * SC, f11.y * SC, qhi[mb][c][3], qlo[mb][c][3]);
        }
    }

    float o[2][8][4];
#pragma unroll
    for (int mb = 0; mb < 2; mb++)
#pragma unroll
        for (int nt = 0; nt < 8; nt++)
#pragma unroll
            for (int i = 0; i < 4; i++) o[mb][nt][i] = 0.f;
    float mst[2][2] = {{-1e30f, -1e30f}, {-1e30f, -1e30f}};
    float lst[2][2] = {{0.f, 0.f}, {0.f, 0.f}};

    const size_t tbase = ((size_t)(b * NH + h) * NTILES) * 1024;

    for (int kt = 0; kt < NTILES; kt++) {
        __syncthreads();
        const size_t tb = tbase + (size_t)kt * 1024;
#pragma unroll
        for (int i = 0; i < 8; i++) {
            int idx = tid + 128 * i;          // 1024 uint4 per array
            int row = idx >> 4, s4 = idx & 15;
            Ksm[row * KVROW + s4] = g_kc4[tb + idx];
            Vsm[row * KVROW + s4] = g_vc4[tb + idx];
        }
        __syncthreads();

        // S = Q @ K^T: each K fragment (one LDS.128) feeds both m-blocks.
        float s[2][8][4];
#pragma unroll
        for (int jn = 0; jn < 8; jn++) {
#pragma unroll
            for (int i = 0; i < 4; i++) { s[0][jn][i] = 0.f; s[1][jn][i] = 0.f; }
            const uint4* kr = Ksm + (jn * 8 + g) * KVROW;
#pragma unroll
            for (int c = 0; c < 4; c++) {
                uint4 kv = kr[c * 4 + tig];
                uint2 bh_ = make_uint2(kv.x, kv.y);
                uint2 bl_ = make_uint2(kv.z, kv.w);
                mma_bf16(s[0][jn], qhi[0][c], bh_);
                mma_bf16(s[0][jn], qlo[0][c], bh_);
                mma_bf16(s[0][jn], qhi[0][c], bl_);
                mma_bf16(s[1][jn], qhi[1][c], bh_);
                mma_bf16(s[1][jn], qlo[1][c], bh_);
                mma_bf16(s[1][jn], qhi[1][c], bl_);
            }
        }

        // Online softmax per m-block (log2 domain) + P pack + PV
#pragma unroll
        for (int mb = 0; mb < 2; mb++) {
            float rmax0 = s[mb][0][0], rmax1 = s[mb][0][2];
#pragma unroll
            for (int jn = 0; jn < 8; jn++) {
                rmax0 = fmaxf(rmax0, fmaxf(s[mb][jn][0], s[mb][jn][1]));
                rmax1 = fmaxf(rmax1, fmaxf(s[mb][jn][2], s[mb][jn][3]));
            }
            rmax0 = fmaxf(rmax0, __shfl_xor_sync(0xffffffffu, rmax0, 1));
            rmax0 = fmaxf(rmax0, __shfl_xor_sync(0xffffffffu, rmax0, 2));
            rmax1 = fmaxf(rmax1, __shfl_xor_sync(0xffffffffu, rmax1, 1));
            rmax1 = fmaxf(rmax1, __shfl_xor_sync(0xffffffffu, rmax1, 2));

            float mn0 = fmaxf(mst[mb][0], rmax0);
            float mn1 = fmaxf(mst[mb][1], rmax1);
            float corr0 = fast_exp2(mst[mb][0] - mn0);
            float corr1 = fast_exp2(mst[mb][1] - mn1);
            mst[mb][0] = mn0; mst[mb][1] = mn1;

            float ps0 = 0.f, ps1 = 0.f;
#pragma unroll
            for (int jn = 0; jn < 8; jn++) {
                s[mb][jn][0] = fast_exp2(s[mb][jn][0] - mn0);
                s[mb][jn][1] = fast_exp2(s[mb][jn][1] - mn0);
                s[mb][jn][2] = fast_exp2(s[mb][jn][2] - mn1);
                s[mb][jn][3] = fast_exp2(s[mb][jn][3] - mn1);
                ps0 += s[mb][jn][0] + s[mb][jn][1];
                ps1 += s[mb][jn][2] + s[mb][jn][3];
            }
            lst[mb][0] = lst[mb][0] * corr0 + ps0;
            lst[mb][1] = lst[mb][1] * corr1 + ps1;
#pragma unroll
            for (int nt = 0; nt < 8; nt++) {
                o[mb][nt][0] *= corr0;
                o[mb][nt][1] *= corr0;
                o[mb][nt][2] *= corr1;
                o[mb][nt][3] *= corr1;
            }

            unsigned phi[4][4], plo[4][4];
#pragma unroll
            for (int c = 0; c < 4; c++) {
                pack_split(s[mb][2*c][0],   s[mb][2*c][1],   phi[c][0], plo[c][0]);
                pack_split(s[mb][2*c][2],   s[mb][2*c][3],   phi[c][1], plo[c][1]);
                pack_split(s[mb][2*c+1][0], s[mb][2*c+1][1], phi[c][2], plo[c][2]);
                pack_split(s[mb][2*c+1][2], s[mb][2*c+1][3], phi[c][3], plo[c][3]);
            }

            // O(mb) += P(mb) @ V
#pragma unroll
            for (int nt = 0; nt < 8; nt++) {
                const uint4* vr = Vsm + (nt * 8 + g) * KVROW;
#pragma unroll
                for (int c = 0; c < 4; c++) {
                    uint4 vv = vr[c * 4 + tig];
                    uint2 bh_ = make_uint2(vv.x, vv.y);
                    uint2 bl_ = make_uint2(vv.z, vv.w);
                    mma_bf16(o[mb][nt], phi[c], bh_);
                    mma_bf16(o[mb][nt], plo[c], bh_);
                    mma_bf16(o[mb][nt], phi[c], bl_);
                }
            }
        }
    }

    // Epilogue: normalize, write packed-A for output projection.
    const int mt = b * (SEQ / 128) + blockIdx.x;
#pragma unroll
    for (int mb = 0; mb < 2; mb++) {
        float li0 = lst[mb][0], li1 = lst[mb][1];
        li0 += __shfl_xor_sync(0xffffffffu, li0, 1);
        li0 += __shfl_xor_sync(0xffffffffu, li0, 2);
        li1 += __shfl_xor_sync(0xffffffffu, li1, 1);
        li1 += __shfl_xor_sync(0xffffffffu, li1, 2);
        const float inv0 = 1.f / li0;
        const float inv1 = 1.f / li1;
        const int mbp = 2 * w + mb;
#pragma unroll
        for (int half = 0; half < 2; half++) {
            const int ki = 2 * h + half;
            uint4* dst = g_apack + ((size_t)(mt * NKI + ki)) * 1024
                                 + mbp * 64 + lane;
#pragma unroll
            for (int ks = 0; ks < 2; ks++) {
                const int nt = half * 4 + ks * 2;
                uint4 hi, lo;
                pack_split(o[mb][nt][0] * inv0,   o[mb][nt][1] * inv0,   hi.x, lo.x);
                pack_split(o[mb][nt][2] * inv1,   o[mb][nt][3] * inv1,   hi.y, lo.y);
                pack_split(o[mb][nt+1][0] * inv0, o[mb][nt+1][1] * inv0, hi.z, lo.z);
                pack_split(o[mb][nt+1][2] * inv1, o[mb][nt+1][3] * inv1, hi.w, lo.w);
                dst[ks * 32]       = hi;
                dst[ks * 32 + 512] = lo;
            }
        }
    }
}

// ---------------------------------------------------------------------------
extern "C" void kernel_launch(void* const* d_in, const int* in_sizes, int n_in,
                              void* d_out, int out_size)
{
    const float* hidden = (const float*)d_in[0];
    const float* rot    = (const float*)d_in[1];
    const float* w_qkv  = (const float*)d_in[2];
    const float* b_qkv  = (const float*)d_in[3];
    const float* nqw    = (const float*)d_in[4];
    const float* nkw    = (const float*)d_in[5];
    const float* w_out  = (const float*)d_in[6];
    const float* b_out  = (const float*)d_in[7];
    const float* hks    = (const float*)d_in[8];
    const int*   ocl    = (const int*)d_in[9];
    float* out = (float*)d_out;

    static float *p_qkv = nullptr, *p_q = nullptr, *p_k = nullptr,
                 *p_v = nullptr;
    static uint4 *p_bq = nullptr, *p_bo = nullptr;
    if (!p_qkv) {
        cudaGetSymbolAddress((void**)&p_qkv,  g_qkv);
        cudaGetSymbolAddress((void**)&p_q,    g_q);
        cudaGetSymbolAddress((void**)&p_k,    g_k);
        cudaGetSymbolAddress((void**)&p_v,    g_v);
        cudaGetSymbolAddress((void**)&p_bq,   g_bpack_qkv);
        cudaGetSymbolAddress((void**)&p_bo,   g_bpack_out);
    }

    // 1) Pack operands
    pack_b_kernel<<<dim3(NKI, QKV3 / 128), 256>>>(w_qkv, p_bq, QKV3);
    pack_b_kernel<<<dim3(NKI, DIMM / 128), 256>>>(w_out, p_bo, DIMM);
    pack_a_kernel<<<dim3(NKI, ROWS / 128), 256>>>(hidden);

    // 2) QKV projection (bf16x3 tensor cores, staggered)
    gemm_bf16x3<<<dim3(QKV3 / 128, ROWS / 128), 256>>>(p_bq, b_qkv, p_qkv, QKV3);

    // 3) RMSNorm + RoPE + history scale + transpose
    preprocess_kernel<<<ROWS, 256>>>(p_qkv, rot, nqw, nkw, hks, ocl,
                                     p_q, p_k, p_v);

    // 4) Pack K,V for attention (interleaved hi/lo)
    pack_kv_kernel<<<dim3(NTILES, NH, BATCH), 256>>>(p_k, p_v);

    // 5) Attention (staggered) -> writes packed A
    attn_tc_kernel<<<dim3(SEQ / 128, NH, BATCH), 128>>>(p_q);

    // 6) Output projection (bf16x3 tensor cores, staggered)
    gemm_bf16x3<<<dim3(DIMM / 128, ROWS / 128), 256>>>(p_bo, b_out, out, DIMM);
}